// round 11
// baseline (speedup 1.0000x reference)
#include <cuda_runtime.h>
#include <math.h>

// Problem constants: B=1048576, M=8, K=3, R=8
#define M 8
#define Kc 3
#define R 8
#define NPAIR 4          // rule pairs (f32x2 lanes = 2 rules)
#define PW 56            // floats per packed pair row (26 entries*2, padded; 16B aligned)
#define TPB 128          // threads per block
#define RPT 4            // rows per thread
#define ROWS_PER_BLOCK (TPB * RPT)   // 512

typedef unsigned long long u64;

static __device__ __forceinline__ u64 pk2(float lo, float hi) {
    u64 r; asm("mov.b64 %0, {%1,%2};" : "=l"(r) : "f"(lo), "f"(hi)); return r;
}
static __device__ __forceinline__ void upk2(u64 v, float& lo, float& hi) {
    asm("mov.b64 {%0,%1}, %2;" : "=f"(lo), "=f"(hi) : "l"(v));
}
static __device__ __forceinline__ u64 fma2(u64 a, u64 b, u64 c) {
    u64 d; asm("fma.rn.f32x2 %0, %1, %2, %3;" : "=l"(d) : "l"(a), "l"(b), "l"(c)); return d;
}
static __device__ __forceinline__ u64 mul2(u64 a, u64 b) {
    u64 d; asm("mul.rn.f32x2 %0, %1, %2;" : "=l"(d) : "l"(a), "l"(b)); return d;
}
static __device__ __forceinline__ float ex2f(float v) {
    float r; asm("ex2.approx.f32 %0, %1;" : "=f"(r) : "f"(v)); return r;
}
static __device__ __forceinline__ float rcpf(float v) {
    float r; asm("rcp.approx.f32 %0, %1;" : "=f"(r) : "f"(v)); return r;
}

__global__ __launch_bounds__(TPB, 5)
void anfis_kernel(const float* __restrict__ x,
                  const float* __restrict__ c,
                  const float* __restrict__ log_sigma,
                  const float* __restrict__ cons,      // (R, M+1)
                  const int*   __restrict__ rules,     // (R, M)
                  float* __restrict__ out, int B)
{
    // Packed entry j (float2 over rule pair p = rules 2p,2p+1):
    //  j=0..7 : a_m = -h*log2(e) ; j=8..15: b_m = 2*h*c*log2(e)
    //  j=16   : k0 = -(sum h*c^2)*log2(e) ; j=17: bias ; j=18..25: w_m
    __shared__ float s_raw[R][26];
    __shared__ __align__(16) float s_pack[NPAIR * PW];

    const int tid = threadIdx.x;
    const float L2E = 1.4426950408889634f;

    if (tid < R) {
        const int r = tid;
        float k0 = 0.f;
        #pragma unroll
        for (int m = 0; m < M; m++) {
            int k = rules[r * M + m];
            float sg = expf(log_sigma[m * Kc + k]) + 1e-6f;
            float h  = 0.5f / (sg * sg);
            float cc = c[m * Kc + k];
            s_raw[r][m]      = -h * L2E;
            s_raw[r][8 + m]  = 2.f * h * cc * L2E;
            k0 -= h * cc * cc;
            s_raw[r][18 + m] = cons[r * (M + 1) + 1 + m];
        }
        s_raw[r][16] = k0 * L2E;
        s_raw[r][17] = cons[r * (M + 1)];
    }
    __syncthreads();
    if (tid < NPAIR * 28) {
        const int p = tid / 28, j = tid % 28;
        float v0 = (j < 26) ? s_raw[2 * p][j]     : 0.f;
        float v1 = (j < 26) ? s_raw[2 * p + 1][j] : 0.f;
        s_pack[p * PW + 2 * j]     = v0;
        s_pack[p * PW + 2 * j + 1] = v1;
    }
    __syncthreads();

    const int b0 = blockIdx.x * ROWS_PER_BLOCK + tid;
    if (b0 >= B) return;
    // B = 1048576 divisible by ROWS_PER_BLOCK=512: all RPT rows valid.

    // ---- load RPT x rows (32B each, coalesced; scalar f32) ----
    float xv[RPT][M];
    #pragma unroll
    for (int i = 0; i < RPT; i++) {
        const int b = b0 + i * TPB;
        const float4 xa = *(const float4*)(x + (size_t)b * M);
        const float4 xb = *(const float4*)(x + (size_t)b * M + 4);
        xv[i][0]=xa.x; xv[i][1]=xa.y; xv[i][2]=xa.z; xv[i][3]=xa.w;
        xv[i][4]=xb.x; xv[i][5]=xb.y; xv[i][6]=xb.z; xv[i][7]=xb.w;
    }

    u64 f2[RPT][NPAIR];        // packed firing strengths per pair
    u64 s2[RPT];               // packed sum of f*yr
    float fs[RPT];
    #pragma unroll
    for (int i = 0; i < RPT; i++) { fs[i] = 0.f; s2[i] = 0ull; }

    #pragma unroll
    for (int p = 0; p < NPAIR; p++) {
        const u64* S = (const u64*)(s_pack + p * PW);  // 26 packed entries, once per 4 rows

        u64 e[RPT], t[RPT];
        #pragma unroll
        for (int i = 0; i < RPT; i++) { e[i] = S[16]; t[i] = S[17]; }

        #pragma unroll
        for (int m = 0; m < M; m++) {
            const u64 A = S[m], Bc = S[8 + m], W = S[18 + m];
            #pragma unroll
            for (int i = 0; i < RPT; i++) {
                const u64 px = pk2(xv[i][m], xv[i][m]);   // rematerializable mov
                e[i] = fma2(fma2(A, px, Bc), px, e[i]);
                t[i] = fma2(W, px, t[i]);
            }
        }

        #pragma unroll
        for (int i = 0; i < RPT; i++) {
            const int b = b0 + i * TPB;
            // y_r stored straight from the packed consequent (8B, 8B-aligned;
            // L2 merges the pair-strided writes into full sectors)
            *(u64*)(out + (size_t)B * 9 + (size_t)b * R + 2 * p) = t[i];

            float ea, eb;
            upk2(e[i], ea, eb);
            const float fa = ex2f(ea), fb = ex2f(eb);
            fs[i] += fa + fb;
            const u64 fp = pk2(fa, fb);
            f2[i][p] = fp;
            s2[i] = fma2(fp, t[i], s2[i]);   // packed sum f*yr
        }
    }

    // ---- normalize + store y, w_norm (packed epilogue) ----
    #pragma unroll
    for (int i = 0; i < RPT; i++) {
        const int b = b0 + i * TPB;
        const float inv = rcpf(fs[i] + 1e-8f);
        const u64 inv2 = pk2(inv, inv);

        ulonglong2 w01, w23;
        w01.x = mul2(f2[i][0], inv2);
        w01.y = mul2(f2[i][1], inv2);
        w23.x = mul2(f2[i][2], inv2);
        w23.y = mul2(f2[i][3], inv2);
        ulonglong2* wo = (ulonglong2*)(out + (size_t)B + (size_t)b * R);
        wo[0] = w01;
        wo[1] = w23;

        float slo, shi;
        upk2(s2[i], slo, shi);
        out[b] = (slo + shi) * inv;
    }
}

extern "C" void kernel_launch(void* const* d_in, const int* in_sizes, int n_in,
                              void* d_out, int out_size)
{
    const float* x         = (const float*)d_in[0];
    const float* c         = (const float*)d_in[1];
    const float* log_sigma = (const float*)d_in[2];
    const float* cons      = (const float*)d_in[3];
    const int*   rules     = (const int*)d_in[4];
    float* out = (float*)d_out;

    const int B = in_sizes[0] / M;   // 1048576
    const int blocks = (B + ROWS_PER_BLOCK - 1) / ROWS_PER_BLOCK;  // 2048
    anfis_kernel<<<blocks, TPB>>>(x, c, log_sigma, cons, rules, out, B);
}

// round 14
// speedup vs baseline: 1.2827x; 1.2827x over previous
#include <cuda_runtime.h>
#include <math.h>

// Problem constants: B=1048576, M=8, K=3, R=8
#define M 8
#define Kc 3
#define R 8
#define NPAIR 4          // rule pairs (f32x2 lanes = 2 rules)
#define PW 56            // floats per packed pair row (26 entries*2, padded; 16B aligned)
#define TPB 128          // threads per block
#define RPT 4            // rows per thread
#define ROWS_PER_BLOCK (TPB * RPT)   // 512

typedef unsigned long long u64;

static __device__ __forceinline__ u64 pk2(float lo, float hi) {
    u64 r; asm("mov.b64 %0, {%1,%2};" : "=l"(r) : "f"(lo), "f"(hi)); return r;
}
static __device__ __forceinline__ void upk2(u64 v, float& lo, float& hi) {
    asm("mov.b64 {%0,%1}, %2;" : "=f"(lo), "=f"(hi) : "l"(v));
}
static __device__ __forceinline__ u64 fma2(u64 a, u64 b, u64 c) {
    u64 d; asm("fma.rn.f32x2 %0, %1, %2, %3;" : "=l"(d) : "l"(a), "l"(b), "l"(c)); return d;
}
static __device__ __forceinline__ u64 mul2(u64 a, u64 b) {
    u64 d; asm("mul.rn.f32x2 %0, %1, %2;" : "=l"(d) : "l"(a), "l"(b)); return d;
}
static __device__ __forceinline__ float ex2f(float v) {
    float r; asm("ex2.approx.f32 %0, %1;" : "=f"(r) : "f"(v)); return r;
}
static __device__ __forceinline__ float rcpf(float v) {
    float r; asm("rcp.approx.f32 %0, %1;" : "=f"(r) : "f"(v)); return r;
}

__global__ __launch_bounds__(TPB, 4)
void anfis_kernel(const float* __restrict__ x,
                  const float* __restrict__ c,
                  const float* __restrict__ log_sigma,
                  const float* __restrict__ cons,      // (R, M+1)
                  const int*   __restrict__ rules,     // (R, M)
                  float* __restrict__ out, int B)
{
    // Packed entry j (float2 over rule pair p = rules 2p,2p+1):
    //  j=0..7 : a_m = -h*log2(e) ; j=8..15: b_m = 2*h*c*log2(e)
    //  j=16   : k0 = -(sum h*c^2)*log2(e) ; j=17: bias ; j=18..25: w_m
    __shared__ float s_raw[R][26];
    __shared__ __align__(16) float s_pack[NPAIR * PW];

    const int tid = threadIdx.x;
    const float L2E = 1.4426950408889634f;

    if (tid < R) {
        const int r = tid;
        float k0 = 0.f;
        #pragma unroll
        for (int m = 0; m < M; m++) {
            int k = rules[r * M + m];
            float sg = expf(log_sigma[m * Kc + k]) + 1e-6f;
            float h  = 0.5f / (sg * sg);
            float cc = c[m * Kc + k];
            s_raw[r][m]      = -h * L2E;
            s_raw[r][8 + m]  = 2.f * h * cc * L2E;
            k0 -= h * cc * cc;
            s_raw[r][18 + m] = cons[r * (M + 1) + 1 + m];
        }
        s_raw[r][16] = k0 * L2E;
        s_raw[r][17] = cons[r * (M + 1)];
    }
    __syncthreads();
    if (tid < NPAIR * 28) {
        const int p = tid / 28, j = tid % 28;
        float v0 = (j < 26) ? s_raw[2 * p][j]     : 0.f;
        float v1 = (j < 26) ? s_raw[2 * p + 1][j] : 0.f;
        s_pack[p * PW + 2 * j]     = v0;
        s_pack[p * PW + 2 * j + 1] = v1;
    }
    __syncthreads();

    const int b0 = blockIdx.x * ROWS_PER_BLOCK + tid;
    if (b0 >= B) return;
    // B = 1048576 divisible by ROWS_PER_BLOCK=512: all RPT rows valid.

    // ---- load RPT x rows (32B each, coalesced; scalar f32) ----
    float xv[RPT][M];
    #pragma unroll
    for (int i = 0; i < RPT; i++) {
        const int b = b0 + i * TPB;
        const float4 xa = *(const float4*)(x + (size_t)b * M);
        const float4 xb = *(const float4*)(x + (size_t)b * M + 4);
        xv[i][0]=xa.x; xv[i][1]=xa.y; xv[i][2]=xa.z; xv[i][3]=xa.w;
        xv[i][4]=xb.x; xv[i][5]=xb.y; xv[i][6]=xb.z; xv[i][7]=xb.w;
    }

    u64 f2[RPT][NPAIR];    // packed firing strengths per pair
    u64 yr2[RPT][NPAIR];   // packed consequents per pair
    u64 s2[RPT];           // packed sum of f*yr
    float fs[RPT];
    #pragma unroll
    for (int i = 0; i < RPT; i++) { fs[i] = 0.f; s2[i] = 0ull; }

    #pragma unroll
    for (int p = 0; p < NPAIR; p++) {
        const u64* S = (const u64*)(s_pack + p * PW);  // 26 packed entries, once per 4 rows

        u64 e[RPT], t[RPT];
        #pragma unroll
        for (int i = 0; i < RPT; i++) { e[i] = S[16]; t[i] = S[17]; }

        #pragma unroll
        for (int m = 0; m < M; m++) {
            const u64 A = S[m], Bc = S[8 + m], W = S[18 + m];
            #pragma unroll
            for (int i = 0; i < RPT; i++) {
                const u64 px = pk2(xv[i][m], xv[i][m]);   // rematerializable mov
                e[i] = fma2(fma2(A, px, Bc), px, e[i]);
                t[i] = fma2(W, px, t[i]);
            }
        }

        #pragma unroll
        for (int i = 0; i < RPT; i++) {
            float ea, eb;
            upk2(e[i], ea, eb);
            const float fa = ex2f(ea), fb = ex2f(eb);
            fs[i] += fa + fb;
            const u64 fp = pk2(fa, fb);
            f2[i][p]  = fp;
            yr2[i][p] = t[i];
            s2[i] = fma2(fp, t[i], s2[i]);   // packed sum f*yr
        }
    }

    // ---- epilogue: full-width coalesced stores only ----
    #pragma unroll
    for (int i = 0; i < RPT; i++) {
        const int b = b0 + i * TPB;

        // y_r: 2x STG.128 per row (same bits as packed consequents)
        ulonglong2* yo = (ulonglong2*)(out + (size_t)B * 9 + (size_t)b * R);
        ulonglong2 y01, y23;
        y01.x = yr2[i][0]; y01.y = yr2[i][1];
        y23.x = yr2[i][2]; y23.y = yr2[i][3];
        yo[0] = y01;
        yo[1] = y23;

        const float inv = rcpf(fs[i] + 1e-8f);
        const u64 inv2 = pk2(inv, inv);

        ulonglong2 w01, w23;
        w01.x = mul2(f2[i][0], inv2);
        w01.y = mul2(f2[i][1], inv2);
        w23.x = mul2(f2[i][2], inv2);
        w23.y = mul2(f2[i][3], inv2);
        ulonglong2* wo = (ulonglong2*)(out + (size_t)B + (size_t)b * R);
        wo[0] = w01;
        wo[1] = w23;

        float slo, shi;
        upk2(s2[i], slo, shi);
        out[b] = (slo + shi) * inv;
    }
}

extern "C" void kernel_launch(void* const* d_in, const int* in_sizes, int n_in,
                              void* d_out, int out_size)
{
    const float* x         = (const float*)d_in[0];
    const float* c         = (const float*)d_in[1];
    const float* log_sigma = (const float*)d_in[2];
    const float* cons      = (const float*)d_in[3];
    const int*   rules     = (const int*)d_in[4];
    float* out = (float*)d_out;

    const int B = in_sizes[0] / M;   // 1048576
    const int blocks = (B + ROWS_PER_BLOCK - 1) / ROWS_PER_BLOCK;  // 2048
    anfis_kernel<<<blocks, TPB>>>(x, c, log_sigma, cons, rules, out, B);
}